// round 6
// baseline (speedup 1.0000x reference)
#include <cuda_runtime.h>
#include <cuda_bf16.h>
#include <cuda_fp8.h>
#include <cstdint>

typedef __nv_bfloat16 bf16;

#define TT 4
#define NN 8192
#define HD 256
#define RPAD 8320        // 1 zero halo row + 8192 data + tail pad (zero)
#define MV 126           // valid output rows per M-tile
#define MT 66            // ceil(8192/126)
#define BN 256
#define PSTRIDE 258
#define INV512 0.001953125f

// smem map (relative to 1024-aligned base S):
//  [0, 32768)        A stages: s -> s*16384 (128 rows x 128B, SW128)
//  [32768, 98304)    B stages: s -> 32768 + s*32768 (256 rows x 128B, SW128)
//  [98304, 230400)   P tile float[128][258]
#define OFF_BST 32768u
#define OFF_P   98304u
#define SMEM_BYTES (230400 + 1024)

// ------------------- device scratch (zero-initialized at load) -------------
// hi planes (bf16, 256/row) and fp8 planes (512/row: [lo8*512 | e4m3(h)])
__device__ __align__(256) bf16          g_Xh[(size_t)TT*RPAD*HD];
__device__ __align__(256) bf16          g_Ah2[(size_t)TT*RPAD*HD];
__device__ __align__(256) bf16          g_Bh[(size_t)TT*RPAD*HD];
__device__ __align__(256) unsigned char g_X8[(size_t)TT*RPAD*512];
__device__ __align__(256) unsigned char g_A8[(size_t)TT*RPAD*512];
__device__ __align__(256) unsigned char g_B8[(size_t)TT*RPAD*512];
// weights: bf16 hi (256/row) and fp8 (512/row: [e4m3(W) | Wlo*512])
__device__ __align__(256) bf16          g_W1h[256*256];
__device__ __align__(256) unsigned char g_W18[256*512];
__device__ __align__(256) bf16          g_WLh[(size_t)8*2048*256];
__device__ __align__(256) unsigned char g_WL8[(size_t)8*2048*512];
__device__ float g_bcat[8*2048];
__device__ float g_tw[10];
__device__ float g_aw[3];
__device__ float g_psum[64*HD];
__device__ float g_pmax[64*HD];

// ------------------- helpers ------------------------------------------------
__device__ __forceinline__ void cp_async16(unsigned dst, const void* src) {
    asm volatile("cp.async.cg.shared.global [%0], [%1], 16;\n" :: "r"(dst), "l"(src));
}
__device__ __forceinline__ void cp_commit() {
    asm volatile("cp.async.commit_group;\n" ::);
}
template <int N>
__device__ __forceinline__ void cp_wait() {
    asm volatile("cp.async.wait_group %0;\n" :: "n"(N));
}
__device__ __forceinline__ void ldsm4(unsigned addr, unsigned& r0, unsigned& r1,
                                      unsigned& r2, unsigned& r3) {
    asm volatile("ldmatrix.sync.aligned.m8n8.x4.shared.b16 {%0,%1,%2,%3}, [%4];\n"
                 : "=r"(r0), "=r"(r1), "=r"(r2), "=r"(r3) : "r"(addr));
}
__device__ __forceinline__ void mma_bf16(float c[4], const unsigned a[4], const unsigned b[2]) {
    asm volatile(
        "mma.sync.aligned.m16n8k16.row.col.f32.bf16.bf16.f32 "
        "{%0,%1,%2,%3}, {%4,%5,%6,%7}, {%8,%9}, {%0,%1,%2,%3};\n"
        : "+f"(c[0]), "+f"(c[1]), "+f"(c[2]), "+f"(c[3])
        : "r"(a[0]), "r"(a[1]), "r"(a[2]), "r"(a[3]), "r"(b[0]), "r"(b[1]));
}
__device__ __forceinline__ void mma_fp8(float c[4], const unsigned a[4], const unsigned b[2]) {
    asm volatile(
        "mma.sync.aligned.m16n8k32.row.col.f32.e4m3.e4m3.f32 "
        "{%0,%1,%2,%3}, {%4,%5,%6,%7}, {%8,%9}, {%0,%1,%2,%3};\n"
        : "+f"(c[0]), "+f"(c[1]), "+f"(c[2]), "+f"(c[3])
        : "r"(a[0]), "r"(a[1]), "r"(a[2]), "r"(a[3]), "r"(b[0]), "r"(b[1]));
}
__device__ __forceinline__ unsigned swz(unsigned b) { return b ^ ((b >> 3) & 0x70); }

__device__ __forceinline__ unsigned char f2e4m3(float v) {
    __nv_fp8_e4m3 t(v);
    return *reinterpret_cast<unsigned char*>(&t);
}
__device__ __forceinline__ float e4m32f(unsigned char b) {
    __nv_fp8_e4m3 t;
    *reinterpret_cast<unsigned char*>(&t) = b;
    return float(t);
}

__device__ __forceinline__ bf16*          hi_plane(int s) { return s==0 ? g_Xh : (s==1 ? g_Ah2 : g_Bh); }
__device__ __forceinline__ unsigned char* f8_plane(int s) { return s==0 ? g_X8 : (s==1 ? g_A8 : g_B8); }

// ------------------- prep kernels ------------------------------------------
__global__ void k_prep(const float* __restrict__ ta, const float* __restrict__ aa) {
    if (threadIdx.x == 0) {
        for (int l = 0; l < 2; l++) {
            float m = -1e30f;
            for (int i = 0; i < 5; i++) m = fmaxf(m, ta[l*5+i]);
            float e[5], s = 0.f;
            for (int i = 0; i < 5; i++) { e[i] = expf(ta[l*5+i] - m); s += e[i]; }
            for (int i = 0; i < 5; i++) g_tw[l*5+i] = e[i] / s;
        }
        float m = -1e30f;
        for (int i = 0; i < 3; i++) m = fmaxf(m, aa[i]);
        float e[3], s = 0.f;
        for (int i = 0; i < 3; i++) { e[i] = expf(aa[i] - m); s += e[i]; }
        for (int i = 0; i < 3; i++) g_aw[i] = e[i] / s;
    }
}

__global__ void k_packx(const float* __restrict__ x) {
    size_t total = (size_t)TT * RPAD * HD;
    for (size_t i = (size_t)blockIdx.x * blockDim.x + threadIdx.x; i < total;
         i += (size_t)gridDim.x * blockDim.x) {
        int ch = (int)(i & 255);
        size_t row = i >> 8;                 // t*RPAD + p
        int p = (int)(row % RPAD);
        float v = 0.f;
        int n = p - 1;
        if (n >= 0 && n < NN) {
            int t = (int)(row / RPAD);
            v = x[((size_t)t * NN + n) * HD + ch];
        }
        bf16 hi = __float2bfloat16(v);
        float lo = v - __bfloat162float(hi);
        g_Xh[i] = hi;
        g_X8[row * 512 + ch]       = f2e4m3(lo * 512.f);
        g_X8[row * 512 + 256 + ch] = f2e4m3(v);
    }
}

__global__ void k_packw1(const float* __restrict__ w) {
    int i = blockIdx.x * blockDim.x + threadIdx.x;  // n*256 + k
    if (i >= 256 * 256) return;
    int n = i >> 8, k = i & 255;
    float v = w[k * HD + n];            // lin1_w[k][n], [Din, H] row-major
    bf16 hi = __float2bfloat16(v);
    float lo = v - __bfloat162float(hi);
    g_W1h[n*256 + k]       = hi;
    g_W18[n*512 + k]       = f2e4m3(v);
    g_W18[n*512 + 256 + k] = f2e4m3(lo * 512.f);
}

__global__ void k_packwl(const float* __restrict__ lw,  const float* __restrict__ lb,
                         const float* __restrict__ rlw, const float* __restrict__ rlb,
                         const float* __restrict__ cw,  const float* __restrict__ cb,
                         const float* __restrict__ rcw, const float* __restrict__ rcb) {
    size_t i = (size_t)blockIdx.x * blockDim.x + threadIdx.x;  // over 8*2048*256
    if (i >= (size_t)8 * 2048 * 256) return;
    int k  = (int)(i & 255);
    int n  = (int)((i >> 8) & 2047);
    int lt = (int)(i >> 19);         // 0..7
    int l = lt >> 2, t = lt & 3;
    int j = n >> 3, op = n & 7;
    float v;
    if (op == 0)      v = lw[(l*256 + k)*256 + j];
    else if (op == 1) v = rlw[((l*4 + t)*256 + k)*256 + j];
    else if (op < 5)  { int kk = op - 2; v = cw[((l*256 + j)*256 + k)*3 + kk]; }
    else              { int kk = op - 5; v = rcw[(((l*4 + t)*256 + j)*256 + k)*3 + kk]; }
    bf16 hi = __float2bfloat16(v);
    float lo = v - __bfloat162float(hi);
    size_t rowi = (size_t)lt * 2048 + n;
    g_WLh[rowi * 256 + k]       = hi;
    g_WL8[rowi * 512 + k]       = f2e4m3(v);
    g_WL8[rowi * 512 + 256 + k] = f2e4m3(lo * 512.f);
    if (k == 0) {
        float b = 0.f;
        if (op == 0)      b = lb[l*256 + j];
        else if (op == 1) b = rlb[(l*4 + t)*256 + j];
        else if (op == 3) b = cb[l*256 + j];
        else if (op == 6) b = rcb[(l*4 + t)*256 + j];
        g_bcat[lt*2048 + n] = b;
    }
}

// ------------------- fused 2-pass GEMM + epilogue ---------------------------
// Pass 1 (bf16): P = h_hi * W_hi^T                 (K=256, 4 chunks of 64)
// Pass 2 (e4m3): C = [hlo*512|h8] * [W8|Wlo*512]^T (K=512, 4 chunks of 128)
// Result: P + C/512.  Both passes: A chunk 128x128B, B chunk 256x128B, SW128.
__global__ void __launch_bounds__(256, 1)
k_gemm(int abuf, int obuf, const float* __restrict__ bias1, int mode, int layer) {
    extern __shared__ char smem_raw[];
    const int tid = threadIdx.x;
    const int wid = tid >> 5, lane = tid & 31;
    const int tn = blockIdx.x, tm = blockIdx.y, t = blockIdx.z;

    unsigned Sraw = (unsigned)__cvta_generic_to_shared(smem_raw);
    unsigned S = (Sraw + 1023u) & ~1023u;
    char* smem = smem_raw + (S - Sraw);

    const bf16*          Ah  = hi_plane(abuf) + (size_t)t * RPAD * HD;
    const unsigned char* A8p = f8_plane(abuf) + (size_t)t * RPAD * 512;
    const char* Bh8;   // pass-1 B base (bf16 rows, 512B stride)
    const char* B88;   // pass-2 B base (fp8 rows, 512B stride)
    if (mode) {
        size_t rb = ((size_t)(layer*4 + t) * 2048 + (size_t)tn * BN);
        Bh8 = (const char*)(g_WLh + rb * 256);
        B88 = (const char*)(g_WL8 + rb * 512);
    } else {
        Bh8 = (const char*)g_W1h;
        B88 = (const char*)g_W18;
    }
    bf16*          Oh  = hi_plane(obuf) + (size_t)t * RPAD * HD;
    unsigned char* O8p = f8_plane(obuf) + (size_t)t * RPAD * 512;
    const int row0 = tm * MV;

    // warp tiling: 8 warps; wm in {0,1} -> 64 rows; wn in 0..3 -> 64 cols
    const int wm = wid & 1, wn = wid >> 1;
    float c[8][4][4];

    // ldmatrix bases (R4-proven pattern, extended to 4 m-frags)
    unsigned abase[4], amask[4], bbase[4], bmask[4];
    const unsigned aK = (unsigned)((lane >> 4) * 16);        // bytes
    const unsigned bK = (unsigned)(((lane >> 3) & 1) * 16);  // bytes
    {
        int r = wm * 64 + ((lane >> 3) & 1) * 8 + (lane & 7);
#pragma unroll
        for (int mf = 0; mf < 4; mf++) {
            unsigned rb = (unsigned)((r + mf * 16) * 128);
            abase[mf] = rb;
            amask[mf] = (rb >> 3) & 0x70;
        }
        int nr = wn * 64 + (lane >> 4) * 8 + (lane & 7);
#pragma unroll
        for (int fp = 0; fp < 4; fp++) {
            unsigned rb = (unsigned)((nr + fp * 16) * 128);
            bbase[fp] = rb;
            bmask[fp] = (rb >> 3) & 0x70;
        }
    }

    auto load_chunk = [&](const char* Abase, const char* Bbase, int ck, int s) {
        unsigned sA = S + (unsigned)s * 16384u;
        unsigned sB = S + OFF_BST + (unsigned)s * 32768u;
        unsigned ko = (unsigned)ck * 128u;
#pragma unroll
        for (int i = 0; i < 4; i++) {
            int idx = tid + i * 256;          // 0..1023
            int r = idx >> 3, cc = idx & 7;
            cp_async16(sA + swz((unsigned)(r * 128 + cc * 16)),
                       Abase + (size_t)(row0 + r) * 512 + ko + cc * 16);
        }
#pragma unroll
        for (int i = 0; i < 8; i++) {
            int idx = tid + i * 256;          // 0..2047
            int r = idx >> 3, cc = idx & 7;
            cp_async16(sB + swz((unsigned)(r * 128 + cc * 16)),
                       Bbase + (size_t)r * 512 + ko + cc * 16);
        }
        cp_commit();
    };

    auto compute_chunk = [&](int s, int pass) {
        unsigned sA = S + (unsigned)s * 16384u;
        unsigned sB = S + OFF_BST + (unsigned)s * 32768u;
#pragma unroll
        for (int ks = 0; ks < 4; ks++) {
            unsigned a[4][4];
#pragma unroll
            for (int mf = 0; mf < 4; mf++) {
                unsigned addr = sA + abase[mf] + (((unsigned)(ks * 32) + aK) ^ amask[mf]);
                ldsm4(addr, a[mf][0], a[mf][1], a[mf][2], a[mf][3]);
            }
            unsigned b[8][2];
#pragma unroll
            for (int fp = 0; fp < 4; fp++) {
                unsigned addr = sB + bbase[fp] + (((unsigned)(ks * 32) + bK) ^ bmask[fp]);
                ldsm4(addr, b[2*fp][0], b[2*fp][1], b[2*fp+1][0], b[2*fp+1][1]);
            }
            if (pass == 0) {
#pragma unroll
                for (int nf = 0; nf < 8; nf++)
#pragma unroll
                    for (int mf = 0; mf < 4; mf++)
                        mma_bf16(c[nf][mf], a[mf], b[nf]);
            } else {
#pragma unroll
                for (int nf = 0; nf < 8; nf++)
#pragma unroll
                    for (int mf = 0; mf < 4; mf++)
                        mma_fp8(c[nf][mf], a[mf], b[nf]);
            }
        }
    };

    auto run_pass = [&](const char* Abase, const char* Bbase, int pass) {
#pragma unroll
        for (int nf = 0; nf < 8; nf++)
#pragma unroll
            for (int mf = 0; mf < 4; mf++)
#pragma unroll
                for (int i = 0; i < 4; i++) c[nf][mf][i] = 0.f;
        load_chunk(Abase, Bbase, 0, 0);
#pragma unroll 1
        for (int ck = 0; ck < 4; ck++) {
            if (ck + 1 < 4) { load_chunk(Abase, Bbase, ck + 1, (ck + 1) & 1); cp_wait<1>(); }
            else            { cp_wait<0>(); }
            __syncthreads();
            compute_chunk(ck & 1, pass);
            __syncthreads();
        }
    };

    float* P = (float*)(smem + OFF_P);
    const int rbase = wm * 64 + (lane >> 2);
    const int cbase = wn * 64 + (lane & 3) * 2;

    // ---- pass 1: bf16 main term -> P ----
    run_pass((const char*)Ah, Bh8, 0);
#pragma unroll
    for (int nf = 0; nf < 8; nf++) {
#pragma unroll
        for (int mf = 0; mf < 4; mf++) {
            int col = cbase + nf * 8;
            int rr = rbase + mf * 16;
            *(float2*)&P[rr * PSTRIDE + col]       = make_float2(c[nf][mf][0], c[nf][mf][1]);
            *(float2*)&P[(rr + 8) * PSTRIDE + col] = make_float2(c[nf][mf][2], c[nf][mf][3]);
        }
    }
    // no barrier needed: each warp re-reads only its own fragments below

    // ---- pass 2: fp8 corrections, combine: P += c / 512 ----
    run_pass((const char*)A8p, B88, 1);
#pragma unroll
    for (int nf = 0; nf < 8; nf++) {
#pragma unroll
        for (int mf = 0; mf < 4; mf++) {
            int col = cbase + nf * 8;
            int rr = rbase + mf * 16;
            float2 v0 = *(float2*)&P[rr * PSTRIDE + col];
            float2 v1 = *(float2*)&P[(rr + 8) * PSTRIDE + col];
            v0.x += c[nf][mf][0] * INV512; v0.y += c[nf][mf][1] * INV512;
            v1.x += c[nf][mf][2] * INV512; v1.y += c[nf][mf][3] * INV512;
            *(float2*)&P[rr * PSTRIDE + col]       = v0;
            *(float2*)&P[(rr + 8) * PSTRIDE + col] = v1;
        }
    }
    __syncthreads();

    // ---- epilogue (same math as validated round-4 kernel) ----
    if (mode == 0) {
        for (int idx = tid; idx < MV * HD; idx += 256) {
            int r = idx / HD + 1;
            int ch = idx % HD;
            int node = row0 + r - 1;
            if (node >= NN) continue;
            float h = P[r * PSTRIDE + ch] + bias1[ch];
            bf16 hi = __float2bfloat16(h);
            float lo = h - __bfloat162float(hi);
            size_t orow = (size_t)(node + 1);
            Oh[orow * HD + ch] = hi;
            O8p[orow * 512 + ch]       = f2e4m3(lo * 512.f);
            O8p[orow * 512 + 256 + ch] = f2e4m3(h);
        }
    } else {
        const float w0 = g_tw[layer*5+0], w1 = g_tw[layer*5+1], w2 = g_tw[layer*5+2],
                    w3 = g_tw[layer*5+3], w4 = g_tw[layer*5+4];
        const float* bc = g_bcat + (layer*4 + t) * 2048 + tn * BN;
        for (int idx = tid; idx < MV * 32; idx += 256) {
            int r = idx / 32 + 1;
            int jc = idx % 32;
            int node = row0 + r - 1;
            if (node >= NN) continue;
            int col = jc * 8;
            const float* Pr = P + r * PSTRIDE;
            float plin = Pr[col + 0];
            float prl  = Pr[col + 1];
            float pc   = Pr[col + 2 - PSTRIDE] + Pr[col + 3] + Pr[col + 4 + PSTRIDE];
            float prc  = Pr[col + 5 - PSTRIDE] + Pr[col + 6] + Pr[col + 7 + PSTRIDE];
            int jg = tn * 32 + jc;
            size_t ia = (size_t)(row0 + r);
            float hold = __bfloat162float(Ah[ia * HD + jg])
                       + e4m32f(A8p[ia * 512 + jg]) * INV512;
            float h = w0 * fmaxf(plin + bc[col + 0], 0.f)
                    + w1 * fmaxf(prl  + bc[col + 1], 0.f)
                    + w2 * fmaxf(pc   + bc[col + 3], 0.f)
                    + w3 * fmaxf(prc  + bc[col + 6], 0.f)
                    + w4 * hold;
            bf16 hi = __float2bfloat16(h);
            float lo = h - __bfloat162float(hi);
            size_t orow = (size_t)(node + 1);
            Oh[orow * HD + jg] = hi;
            O8p[orow * 512 + jg]       = f2e4m3(lo * 512.f);
            O8p[orow * 512 + 256 + jg] = f2e4m3(h);
        }
    }
}

// ------------------- aggregation -------------------------------------------
__global__ void k_agg1() {
    int t = blockIdx.x >> 4;
    int chunk = blockIdx.x & 15;
    int ch = threadIdx.x;
    const bf16* Hh          = g_Ah2 + (size_t)t * RPAD * HD;
    const unsigned char* H8 = g_A8  + (size_t)t * RPAD * 512;
    float s = 0.f, mx = -3.4e38f;
    int n0 = chunk * 512;
    for (int n = n0; n < n0 + 512; n++) {
        size_t row = (size_t)(n + 1);
        float v = __bfloat162float(Hh[row * HD + ch]) + e4m32f(H8[row * 512 + ch]) * INV512;
        s += v;
        mx = fmaxf(mx, v);
    }
    g_psum[blockIdx.x * HD + ch] = s;
    g_pmax[blockIdx.x * HD + ch] = mx;
}

__global__ void k_agg2(const float* __restrict__ ow, const float* __restrict__ ob,
                       float* __restrict__ out) {
    __shared__ float agg[HD];
    int j = threadIdx.x;
    float s = 0.f, mx = -3.4e38f;
    for (int b = 0; b < 64; b++) {
        s += g_psum[b * HD + j];
        mx = fmaxf(mx, g_pmax[b * HD + j]);
    }
    agg[j] = g_aw[0] * s + g_aw[1] * (s / 32768.f) + g_aw[2] * mx;
    __syncthreads();
    if (j < 64) {
        float acc = ob[j];
        for (int k = 0; k < HD; k++) acc += agg[k] * ow[k * 64 + j];
        out[j] = acc;
    }
}

// ------------------- launcher ----------------------------------------------
extern "C" void kernel_launch(void* const* d_in, const int* in_sizes, int n_in,
                              void* d_out, int out_size) {
    (void)in_sizes; (void)n_in; (void)out_size;
    const float* x          = (const float*)d_in[0];
    const float* lin1_w     = (const float*)d_in[1];
    const float* lin1_b     = (const float*)d_in[2];
    const float* lin_w      = (const float*)d_in[3];
    const float* lin_b      = (const float*)d_in[4];
    const float* rel_lin_w  = (const float*)d_in[5];
    const float* rel_lin_b  = (const float*)d_in[6];
    const float* conv_w     = (const float*)d_in[7];
    const float* conv_b     = (const float*)d_in[8];
    const float* rel_conv_w = (const float*)d_in[9];
    const float* rel_conv_b = (const float*)d_in[10];
    const float* out_w      = (const float*)d_in[11];
    const float* out_b      = (const float*)d_in[12];
    const float* trans_arch = (const float*)d_in[13];
    const float* agg_arch   = (const float*)d_in[14];
    float* out = (float*)d_out;

    cudaFuncSetAttribute(k_gemm, cudaFuncAttributeMaxDynamicSharedMemorySize, SMEM_BYTES);

    k_prep<<<1, 32>>>(trans_arch, agg_arch);
    k_packx<<<4096, 256>>>(x);
    k_packw1<<<256, 256>>>(lin1_w);
    k_packwl<<<(8 * 2048 * 256 + 255) / 256, 256>>>(lin_w, lin_b, rel_lin_w, rel_lin_b,
                                                    conv_w, conv_b, rel_conv_w, rel_conv_b);

    dim3 g1(1, MT, TT), gl(8, MT, TT);
    // lin1: X -> A
    k_gemm<<<g1, 256, SMEM_BYTES>>>(0, 1, lin1_b, 0, 0);
    // layer 0: A -> B
    k_gemm<<<gl, 256, SMEM_BYTES>>>(1, 2, nullptr, 1, 0);
    // layer 1: B -> A
    k_gemm<<<gl, 256, SMEM_BYTES>>>(2, 1, nullptr, 1, 1);

    k_agg1<<<64, 256>>>();
    k_agg2<<<1, 256>>>(out_w, out_b, out);
}

// round 8
// speedup vs baseline: 2.0952x; 2.0952x over previous
#include <cuda_runtime.h>
#include <cuda_fp16.h>
#include <cstdint>

typedef __half h16;

#define TT 4
#define NN 8192
#define HD 256
#define RPAD 8320        // 1 zero halo row + 8192 data + tail pad (zero)
#define KT 256           // single fp16 term: K = 256
#define BM 128
#define BN 256
#define BK 64
#define NCH 4            // 256/64
#define MV 126           // valid output rows per M-tile
#define MT 66            // ceil(8192/126)
#define PSTRIDE 258
#define SMEM_BYTES (BM*PSTRIDE*4)            // 132096 (P tile; aliases stages)
#define STAGE_BYTES ((BM*BK + BN*BK)*2)      // 49152
#define A_STAGE_BYTES (BM*BK*2)              // 16384

// ------------------- device scratch (zero-initialized at load) -------------
__device__ __align__(256) h16 g_X[(size_t)TT*RPAD*HD];
__device__ __align__(256) h16 g_A[(size_t)TT*RPAD*HD];
__device__ __align__(256) h16 g_B[(size_t)TT*RPAD*HD];
__device__ __align__(256) h16 g_W1[HD*KT];
__device__ __align__(256) h16 g_WL[(size_t)8*2048*KT];
__device__ float g_bcat[8*2048];
__device__ float g_tw[10];
__device__ float g_aw[3];
__device__ float g_psum[64*HD];
__device__ float g_pmax[64*HD];

// ------------------- PTX helpers -------------------------------------------
__device__ __forceinline__ void cp_async16(unsigned dst, const void* src) {
    asm volatile("cp.async.cg.shared.global [%0], [%1], 16;\n" :: "r"(dst), "l"(src));
}
__device__ __forceinline__ void cp_commit() {
    asm volatile("cp.async.commit_group;\n" ::);
}
template <int N>
__device__ __forceinline__ void cp_wait() {
    asm volatile("cp.async.wait_group %0;\n" :: "n"(N));
}
__device__ __forceinline__ void ldsm4(unsigned addr, unsigned& r0, unsigned& r1,
                                      unsigned& r2, unsigned& r3) {
    asm volatile("ldmatrix.sync.aligned.m8n8.x4.shared.b16 {%0,%1,%2,%3}, [%4];\n"
                 : "=r"(r0), "=r"(r1), "=r"(r2), "=r"(r3) : "r"(addr));
}
__device__ __forceinline__ void mma16816(float c[4], const unsigned a[4], const unsigned b[2]) {
    asm volatile(
        "mma.sync.aligned.m16n8k16.row.col.f32.f16.f16.f32 "
        "{%0,%1,%2,%3}, {%4,%5,%6,%7}, {%8,%9}, {%0,%1,%2,%3};\n"
        : "+f"(c[0]), "+f"(c[1]), "+f"(c[2]), "+f"(c[3])
        : "r"(a[0]), "r"(a[1]), "r"(a[2]), "r"(a[3]), "r"(b[0]), "r"(b[1]));
}
__device__ __forceinline__ unsigned swz(unsigned b) { return b ^ ((b >> 3) & 0x70); }

__device__ __forceinline__ h16* sel_buf(int s) { return s==0 ? g_X : (s==1 ? g_A : g_B); }

// ------------------- prep kernels ------------------------------------------
__global__ void k_prep(const float* __restrict__ ta, const float* __restrict__ aa) {
    if (threadIdx.x == 0) {
        for (int l = 0; l < 2; l++) {
            float m = -1e30f;
            for (int i = 0; i < 5; i++) m = fmaxf(m, ta[l*5+i]);
            float e[5], s = 0.f;
            for (int i = 0; i < 5; i++) { e[i] = expf(ta[l*5+i] - m); s += e[i]; }
            for (int i = 0; i < 5; i++) g_tw[l*5+i] = e[i] / s;
        }
        float m = -1e30f;
        for (int i = 0; i < 3; i++) m = fmaxf(m, aa[i]);
        float e[3], s = 0.f;
        for (int i = 0; i < 3; i++) { e[i] = expf(aa[i] - m); s += e[i]; }
        for (int i = 0; i < 3; i++) g_aw[i] = e[i] / s;
    }
}

__global__ void k_packx(const float* __restrict__ x) {
    size_t total = (size_t)TT * RPAD * HD;
    for (size_t i = (size_t)blockIdx.x * blockDim.x + threadIdx.x; i < total;
         i += (size_t)gridDim.x * blockDim.x) {
        int ch = (int)(i & 255);
        size_t row = i >> 8;                 // t*RPAD + p
        int p = (int)(row % RPAD);
        float v = 0.f;
        int n = p - 1;
        if (n >= 0 && n < NN) {
            int t = (int)(row / RPAD);
            v = x[((size_t)t * NN + n) * HD + ch];
        }
        g_X[i] = __float2half(v);
    }
}

__global__ void k_packw1(const float* __restrict__ w) {
    int i = blockIdx.x * blockDim.x + threadIdx.x;  // n*256 + k
    if (i >= HD * HD) return;
    int n = i >> 8, k = i & 255;
    g_W1[n*KT + k] = __float2half(w[k * HD + n]);   // lin1_w[k][n], [Din, H] row-major
}

__global__ void k_packwl(const float* __restrict__ lw,  const float* __restrict__ lb,
                         const float* __restrict__ rlw, const float* __restrict__ rlb,
                         const float* __restrict__ cw,  const float* __restrict__ cb,
                         const float* __restrict__ rcw, const float* __restrict__ rcb) {
    size_t i = (size_t)blockIdx.x * blockDim.x + threadIdx.x;  // over 8*2048*256
    if (i >= (size_t)8 * 2048 * 256) return;
    int k  = (int)(i & 255);
    int n  = (int)((i >> 8) & 2047);
    int lt = (int)(i >> 19);         // 0..7
    int l = lt >> 2, t = lt & 3;
    int j = n >> 3, op = n & 7;
    float v;
    if (op == 0)      v = lw[(l*256 + k)*256 + j];
    else if (op == 1) v = rlw[((l*4 + t)*256 + k)*256 + j];
    else if (op < 5)  { int kk = op - 2; v = cw[((l*256 + j)*256 + k)*3 + kk]; }
    else              { int kk = op - 5; v = rcw[(((l*4 + t)*256 + j)*256 + k)*3 + kk]; }
    g_WL[((size_t)lt * 2048 + n) * KT + k] = __float2half(v);
    if (k == 0) {
        float b = 0.f;
        if (op == 0)      b = lb[l*256 + j];
        else if (op == 1) b = rlb[(l*4 + t)*256 + j];
        else if (op == 3) b = cb[l*256 + j];
        else if (op == 6) b = rcb[(l*4 + t)*256 + j];
        g_bcat[lt*2048 + n] = b;
    }
}

// ------------------- fused GEMM + epilogue ---------------------------------
// P[128 x BN] = A[128 x 256] * B[BN x 256]^T, fp16 operands, fp32 accumulate
// mode 0: lin1 (BN covers all 256 channels, bias only)
// mode 1: layer (BN covers 32 channels x 8 op taps; relu/conv/identity mix)
__global__ void __launch_bounds__(512, 1)
k_gemm(int abuf, int obuf, const float* __restrict__ bias1, int mode, int layer) {
    extern __shared__ char smem[];
    const int tid = threadIdx.x;
    const int wid = tid >> 5, lane = tid & 31;
    const int tn = blockIdx.x, tm = blockIdx.y, t = blockIdx.z;

    const h16* Ah = sel_buf(abuf) + (size_t)t * RPAD * HD;
    const h16* Bp = mode ? (g_WL + ((size_t)(layer*4 + t) * 2048 + (size_t)tn * BN) * KT)
                         : g_W1;
    h16* Oh = sel_buf(obuf);

    const int row0 = tm * MV;   // global padded row of A-tile row 0
    unsigned sbase = (unsigned)__cvta_generic_to_shared(smem);

    float c[8][2][4];
#pragma unroll
    for (int a = 0; a < 8; a++)
#pragma unroll
        for (int b = 0; b < 2; b++)
#pragma unroll
            for (int i = 0; i < 4; i++) c[a][b][i] = 0.f;

    auto load_chunk = [&](int ck, int stage) {
        unsigned sA = sbase + stage * STAGE_BYTES;
        unsigned sB = sA + A_STAGE_BYTES;
        int kofs = ck * 64;
#pragma unroll
        for (int i = 0; i < 2; i++) {
            int idx = tid + i * 512;          // 0..1023
            int r = idx >> 3, cc = idx & 7;
            const h16* src = Ah + (size_t)(row0 + r) * HD + kofs + cc * 8;
            cp_async16(sA + swz((unsigned)(r * 128 + cc * 16)), src);
        }
#pragma unroll
        for (int i = 0; i < 4; i++) {
            int idx = tid + i * 512;          // 0..2047
            int r = idx >> 3, cc = idx & 7;
            const h16* src = Bp + (size_t)r * KT + kofs + cc * 8;
            cp_async16(sB + swz((unsigned)(r * 128 + cc * 16)), src);
        }
        cp_commit();
    };

    // ldmatrix address bases (k-offset XOR mask depends only on row)
    const int wm = wid & 3, wn = wid >> 2;
    unsigned abase[2], amask[2], bbase[4], bmask[4];
    const unsigned aK = (unsigned)((lane >> 4) * 16);        // bytes
    const unsigned bK = (unsigned)(((lane >> 3) & 1) * 16);  // bytes
    {
        int r = wm * 32 + ((lane >> 3) & 1) * 8 + (lane & 7);
#pragma unroll
        for (int mf = 0; mf < 2; mf++) {
            unsigned rb = (unsigned)((r + mf * 16) * 128);
            abase[mf] = rb;
            amask[mf] = (rb >> 3) & 0x70;
        }
        int nr = wn * 64 + (lane >> 4) * 8 + (lane & 7);
#pragma unroll
        for (int fp = 0; fp < 4; fp++) {
            unsigned rb = (unsigned)((nr + fp * 16) * 128);
            bbase[fp] = rb;
            bmask[fp] = (rb >> 3) & 0x70;
        }
    }

    auto compute_chunk = [&](int stage) {
        unsigned sA = sbase + stage * STAGE_BYTES;
        unsigned sB = sA + A_STAGE_BYTES;
#pragma unroll
        for (int ks = 0; ks < 4; ks++) {
            unsigned a[2][4];
#pragma unroll
            for (int mf = 0; mf < 2; mf++) {
                unsigned addr = sA + abase[mf] + (((unsigned)(ks * 32) + aK) ^ amask[mf]);
                ldsm4(addr, a[mf][0], a[mf][1], a[mf][2], a[mf][3]);
            }
            unsigned b[8][2];
#pragma unroll
            for (int fp = 0; fp < 4; fp++) {
                unsigned addr = sB + bbase[fp] + (((unsigned)(ks * 32) + bK) ^ bmask[fp]);
                ldsm4(addr, b[2*fp][0], b[2*fp][1], b[2*fp+1][0], b[2*fp+1][1]);
            }
#pragma unroll
            for (int nf = 0; nf < 8; nf++)
#pragma unroll
                for (int mf = 0; mf < 2; mf++)
                    mma16816(c[nf][mf], a[mf], b[nf]);
        }
    };

    load_chunk(0, 0);
#pragma unroll 1
    for (int ck = 0; ck < NCH; ck++) {
        if (ck + 1 < NCH) { load_chunk(ck + 1, (ck + 1) & 1); cp_wait<1>(); }
        else              { cp_wait<0>(); }
        __syncthreads();
        compute_chunk(ck & 1);
        __syncthreads();
    }

    // ---- write accumulators to smem P tile (aliases stage buffers) ----
    float* P = (float*)smem;
    {
        int rbase = wm * 32 + (lane >> 2);
        int cbase = wn * 64 + (lane & 3) * 2;
#pragma unroll
        for (int nf = 0; nf < 8; nf++) {
#pragma unroll
            for (int mf = 0; mf < 2; mf++) {
                int col = cbase + nf * 8;
                int rr = rbase + mf * 16;
                *(float2*)&P[rr * PSTRIDE + col]       = make_float2(c[nf][mf][0], c[nf][mf][1]);
                *(float2*)&P[(rr + 8) * PSTRIDE + col] = make_float2(c[nf][mf][2], c[nf][mf][3]);
            }
        }
    }
    __syncthreads();

    if (mode == 0) {
        for (int idx = tid; idx < MV * HD; idx += 512) {
            int r = idx / HD + 1;
            int ch = idx % HD;
            int node = row0 + r - 1;
            if (node >= NN) continue;
            float h = P[r * PSTRIDE + ch] + bias1[ch];
            size_t o = (size_t)t * RPAD * HD + (size_t)(node + 1) * HD + ch;
            Oh[o] = __float2half(h);
        }
    } else {
        const float w0 = g_tw[layer*5+0], w1 = g_tw[layer*5+1], w2 = g_tw[layer*5+2],
                    w3 = g_tw[layer*5+3], w4 = g_tw[layer*5+4];
        const float* bc = g_bcat + (layer*4 + t) * 2048 + tn * BN;
        for (int idx = tid; idx < MV * 32; idx += 512) {
            int r = idx / 32 + 1;
            int jc = idx % 32;
            int node = row0 + r - 1;
            if (node >= NN) continue;
            int col = jc * 8;
            const float* Pr = P + r * PSTRIDE;
            float plin = Pr[col + 0];
            float prl  = Pr[col + 1];
            float pc   = Pr[col + 2 - PSTRIDE] + Pr[col + 3] + Pr[col + 4 + PSTRIDE];
            float prc  = Pr[col + 5 - PSTRIDE] + Pr[col + 6] + Pr[col + 7 + PSTRIDE];
            int jg = tn * 32 + jc;
            size_t ia = (size_t)(row0 + r) * HD + jg;  // plane-relative
            float hold = __half2float(Ah[ia]);
            float h = w0 * fmaxf(plin + bc[col + 0], 0.f)
                    + w1 * fmaxf(prl  + bc[col + 1], 0.f)
                    + w2 * fmaxf(pc   + bc[col + 3], 0.f)
                    + w3 * fmaxf(prc  + bc[col + 6], 0.f)
                    + w4 * hold;
            size_t o = (size_t)t * RPAD * HD + (size_t)(node + 1) * HD + jg;
            Oh[o] = __float2half(h);
        }
    }
}

// ------------------- aggregation -------------------------------------------
__global__ void k_agg1() {
    int t = blockIdx.x >> 4;
    int chunk = blockIdx.x & 15;
    int ch = threadIdx.x;
    const h16* Hh = g_A + (size_t)t * RPAD * HD;
    float s = 0.f, mx = -3.4e38f;
    int n0 = chunk * 512;
    for (int n = n0; n < n0 + 512; n++) {
        float v = __half2float(Hh[(size_t)(n + 1) * HD + ch]);
        s += v;
        mx = fmaxf(mx, v);
    }
    g_psum[blockIdx.x * HD + ch] = s;
    g_pmax[blockIdx.x * HD + ch] = mx;
}

__global__ void k_agg2(const float* __restrict__ ow, const float* __restrict__ ob,
                       float* __restrict__ out) {
    __shared__ float agg[HD];
    int j = threadIdx.x;
    float s = 0.f, mx = -3.4e38f;
    for (int b = 0; b < 64; b++) {
        s += g_psum[b * HD + j];
        mx = fmaxf(mx, g_pmax[b * HD + j]);
    }
    agg[j] = g_aw[0] * s + g_aw[1] * (s / 32768.f) + g_aw[2] * mx;
    __syncthreads();
    if (j < 64) {
        float acc = ob[j];
        for (int k = 0; k < HD; k++) acc += agg[k] * ow[k * 64 + j];
        out[j] = acc;
    }
}

// ------------------- launcher ----------------------------------------------
extern "C" void kernel_launch(void* const* d_in, const int* in_sizes, int n_in,
                              void* d_out, int out_size) {
    (void)in_sizes; (void)n_in; (void)out_size;
    const float* x          = (const float*)d_in[0];
    const float* lin1_w     = (const float*)d_in[1];
    const float* lin1_b     = (const float*)d_in[2];
    const float* lin_w      = (const float*)d_in[3];
    const float* lin_b      = (const float*)d_in[4];
    const float* rel_lin_w  = (const float*)d_in[5];
    const float* rel_lin_b  = (const float*)d_in[6];
    const float* conv_w     = (const float*)d_in[7];
    const float* conv_b     = (const float*)d_in[8];
    const float* rel_conv_w = (const float*)d_in[9];
    const float* rel_conv_b = (const float*)d_in[10];
    const float* out_w      = (const float*)d_in[11];
    const float* out_b      = (const float*)d_in[12];
    const float* trans_arch = (const float*)d_in[13];
    const float* agg_arch   = (const float*)d_in[14];
    float* out = (float*)d_out;

    cudaFuncSetAttribute(k_gemm, cudaFuncAttributeMaxDynamicSharedMemorySize, SMEM_BYTES);

    k_prep<<<1, 32>>>(trans_arch, agg_arch);
    k_packx<<<4096, 256>>>(x);
    k_packw1<<<256, 256>>>(lin1_w);
    k_packwl<<<(8 * 2048 * 256 + 255) / 256, 256>>>(lin_w, lin_b, rel_lin_w, rel_lin_b,
                                                    conv_w, conv_b, rel_conv_w, rel_conv_b);

    dim3 g1(1, MT, TT), gl(8, MT, TT);
    // lin1: X -> A
    k_gemm<<<g1, 512, SMEM_BYTES>>>(0, 1, lin1_b, 0, 0);
    // layer 0: A -> B
    k_gemm<<<gl, 512, SMEM_BYTES>>>(1, 2, nullptr, 1, 0);
    // layer 1: B -> A
    k_gemm<<<gl, 512, SMEM_BYTES>>>(2, 1, nullptr, 1, 1);

    k_agg1<<<64, 256>>>();
    k_agg2<<<1, 256>>>(out_w, out_b, out);
}

// round 9
// speedup vs baseline: 2.5820x; 1.2323x over previous
#include <cuda_runtime.h>
#include <cuda_fp16.h>
#include <cstdint>

typedef __half h16;

#define TT 4
#define NN 8192
#define HD 256
#define RPAD 8320        // 1 zero halo row + 8192 data + tail pad (zero)
#define KT 256           // single fp16 term: K = 256
#define BM 128
#define BN 128
#define BK 64
#define NCH 4            // 256/64
#define MV 126           // valid output rows per M-tile
#define MT 66            // ceil(8192/126)
#define PSTRIDE 130
#define SMEM_BYTES (BM*PSTRIDE*4)            // 66560 (P tile; aliases stages)
#define STAGE_BYTES ((BM*BK + BN*BK)*2)      // 32768
#define A_STAGE_BYTES (BM*BK*2)              // 16384

// ------------------- device scratch (zero-initialized at load) -------------
__device__ __align__(256) h16 g_X[(size_t)TT*RPAD*HD];
__device__ __align__(256) h16 g_A[(size_t)TT*RPAD*HD];
__device__ __align__(256) h16 g_B[(size_t)TT*RPAD*HD];
__device__ __align__(256) h16 g_W1[HD*KT];
__device__ __align__(256) h16 g_WL[(size_t)8*2048*KT];
__device__ float g_bcat[8*2048];
__device__ float g_tw[10];
__device__ float g_aw[3];
__device__ float g_psum[64*HD];
__device__ float g_pmax[64*HD];

// ------------------- PTX helpers -------------------------------------------
__device__ __forceinline__ void cp_async16(unsigned dst, const void* src) {
    asm volatile("cp.async.cg.shared.global [%0], [%1], 16;\n" :: "r"(dst), "l"(src));
}
__device__ __forceinline__ void cp_commit() {
    asm volatile("cp.async.commit_group;\n" ::);
}
template <int N>
__device__ __forceinline__ void cp_wait() {
    asm volatile("cp.async.wait_group %0;\n" :: "n"(N));
}
__device__ __forceinline__ void ldsm4(unsigned addr, unsigned& r0, unsigned& r1,
                                      unsigned& r2, unsigned& r3) {
    asm volatile("ldmatrix.sync.aligned.m8n8.x4.shared.b16 {%0,%1,%2,%3}, [%4];\n"
                 : "=r"(r0), "=r"(r1), "=r"(r2), "=r"(r3) : "r"(addr));
}
__device__ __forceinline__ void mma16816(float c[4], const unsigned a[4], const unsigned b[2]) {
    asm volatile(
        "mma.sync.aligned.m16n8k16.row.col.f32.f16.f16.f32 "
        "{%0,%1,%2,%3}, {%4,%5,%6,%7}, {%8,%9}, {%0,%1,%2,%3};\n"
        : "+f"(c[0]), "+f"(c[1]), "+f"(c[2]), "+f"(c[3])
        : "r"(a[0]), "r"(a[1]), "r"(a[2]), "r"(a[3]), "r"(b[0]), "r"(b[1]));
}
__device__ __forceinline__ unsigned swz(unsigned b) { return b ^ ((b >> 3) & 0x70); }

__device__ __forceinline__ h16* sel_buf(int s) { return s==0 ? g_X : (s==1 ? g_A : g_B); }

// ------------------- prep kernels ------------------------------------------
__global__ void k_prep(const float* __restrict__ ta, const float* __restrict__ aa) {
    if (threadIdx.x == 0) {
        for (int l = 0; l < 2; l++) {
            float m = -1e30f;
            for (int i = 0; i < 5; i++) m = fmaxf(m, ta[l*5+i]);
            float e[5], s = 0.f;
            for (int i = 0; i < 5; i++) { e[i] = expf(ta[l*5+i] - m); s += e[i]; }
            for (int i = 0; i < 5; i++) g_tw[l*5+i] = e[i] / s;
        }
        float m = -1e30f;
        for (int i = 0; i < 3; i++) m = fmaxf(m, aa[i]);
        float e[3], s = 0.f;
        for (int i = 0; i < 3; i++) { e[i] = expf(aa[i] - m); s += e[i]; }
        for (int i = 0; i < 3; i++) g_aw[i] = e[i] / s;
    }
}

__global__ void k_packx(const float* __restrict__ x) {
    size_t total = (size_t)TT * RPAD * HD;
    for (size_t i = (size_t)blockIdx.x * blockDim.x + threadIdx.x; i < total;
         i += (size_t)gridDim.x * blockDim.x) {
        int ch = (int)(i & 255);
        size_t row = i >> 8;                 // t*RPAD + p
        int p = (int)(row % RPAD);
        float v = 0.f;
        int n = p - 1;
        if (n >= 0 && n < NN) {
            int t = (int)(row / RPAD);
            v = x[((size_t)t * NN + n) * HD + ch];
        }
        g_X[i] = __float2half(v);
    }
}

__global__ void k_packw1(const float* __restrict__ w) {
    int i = blockIdx.x * blockDim.x + threadIdx.x;  // n*256 + k
    if (i >= HD * HD) return;
    int n = i >> 8, k = i & 255;
    g_W1[n*KT + k] = __float2half(w[k * HD + n]);   // lin1_w[k][n], [Din, H] row-major
}

__global__ void k_packwl(const float* __restrict__ lw,  const float* __restrict__ lb,
                         const float* __restrict__ rlw, const float* __restrict__ rlb,
                         const float* __restrict__ cw,  const float* __restrict__ cb,
                         const float* __restrict__ rcw, const float* __restrict__ rcb) {
    size_t i = (size_t)blockIdx.x * blockDim.x + threadIdx.x;  // over 8*2048*256
    if (i >= (size_t)8 * 2048 * 256) return;
    int k  = (int)(i & 255);
    int n  = (int)((i >> 8) & 2047);
    int lt = (int)(i >> 19);         // 0..7
    int l = lt >> 2, t = lt & 3;
    int j = n >> 3, op = n & 7;
    float v;
    if (op == 0)      v = lw[(l*256 + k)*256 + j];
    else if (op == 1) v = rlw[((l*4 + t)*256 + k)*256 + j];
    else if (op < 5)  { int kk = op - 2; v = cw[((l*256 + j)*256 + k)*3 + kk]; }
    else              { int kk = op - 5; v = rcw[(((l*4 + t)*256 + j)*256 + k)*3 + kk]; }
    g_WL[((size_t)lt * 2048 + n) * KT + k] = __float2half(v);
    if (k == 0) {
        float b = 0.f;
        if (op == 0)      b = lb[l*256 + j];
        else if (op == 1) b = rlb[(l*4 + t)*256 + j];
        else if (op == 3) b = cb[l*256 + j];
        else if (op == 6) b = rcb[(l*4 + t)*256 + j];
        g_bcat[lt*2048 + n] = b;
    }
}

// ------------------- fused GEMM + epilogue ---------------------------------
// P[128 x 128] = A[128 x 256] * B[128 x 256]^T, fp16 operands, fp32 accumulate
// mode 0: lin1 (tn tile covers 128 of 256 channels, bias only)
// mode 1: layer (tn tile covers 16 channels x 8 op taps; relu/conv/identity mix)
// 256 threads, 2 CTAs/SM: second CTA's mainloop hides this CTA's bubbles.
__global__ void __launch_bounds__(256, 2)
k_gemm(int abuf, int obuf, const float* __restrict__ bias1, int mode, int layer) {
    extern __shared__ char smem[];
    const int tid = threadIdx.x;
    const int wid = tid >> 5, lane = tid & 31;
    const int tn = blockIdx.x, tm = blockIdx.y, t = blockIdx.z;

    const h16* Ah = sel_buf(abuf) + (size_t)t * RPAD * HD;
    const h16* Bp = mode ? (g_WL + ((size_t)(layer*4 + t) * 2048 + (size_t)tn * BN) * KT)
                         : (g_W1 + (size_t)tn * BN * KT);
    h16* Oh = sel_buf(obuf);

    const int row0 = tm * MV;   // global padded row of A-tile row 0
    unsigned sbase = (unsigned)__cvta_generic_to_shared(smem);

    float c[8][2][4];
#pragma unroll
    for (int a = 0; a < 8; a++)
#pragma unroll
        for (int b = 0; b < 2; b++)
#pragma unroll
            for (int i = 0; i < 4; i++) c[a][b][i] = 0.f;

    auto load_chunk = [&](int ck, int stage) {
        unsigned sA = sbase + stage * STAGE_BYTES;
        unsigned sB = sA + A_STAGE_BYTES;
        int kofs = ck * 64;
#pragma unroll
        for (int i = 0; i < 4; i++) {
            int idx = tid + i * 256;          // 0..1023 (128 rows x 8 cols)
            int r = idx >> 3, cc = idx & 7;
            const h16* src = Ah + (size_t)(row0 + r) * HD + kofs + cc * 8;
            cp_async16(sA + swz((unsigned)(r * 128 + cc * 16)), src);
        }
#pragma unroll
        for (int i = 0; i < 4; i++) {
            int idx = tid + i * 256;          // 0..1023
            int r = idx >> 3, cc = idx & 7;
            const h16* src = Bp + (size_t)r * KT + kofs + cc * 8;
            cp_async16(sB + swz((unsigned)(r * 128 + cc * 16)), src);
        }
        cp_commit();
    };

    // ldmatrix address bases (k-offset XOR mask depends only on row)
    const int wm = wid & 3, wn = wid >> 2;   // wm: 4 x 32 rows, wn: 2 x 64 cols
    unsigned abase[2], amask[2], bbase[4], bmask[4];
    const unsigned aK = (unsigned)((lane >> 4) * 16);        // bytes
    const unsigned bK = (unsigned)(((lane >> 3) & 1) * 16);  // bytes
    {
        int r = wm * 32 + ((lane >> 3) & 1) * 8 + (lane & 7);
#pragma unroll
        for (int mf = 0; mf < 2; mf++) {
            unsigned rb = (unsigned)((r + mf * 16) * 128);
            abase[mf] = rb;
            amask[mf] = (rb >> 3) & 0x70;
        }
        int nr = wn * 64 + (lane >> 4) * 8 + (lane & 7);
#pragma unroll
        for (int fp = 0; fp < 4; fp++) {
            unsigned rb = (unsigned)((nr + fp * 16) * 128);
            bbase[fp] = rb;
            bmask[fp] = (rb >> 3) & 0x70;
        }
    }

    auto compute_chunk = [&](int stage) {
        unsigned sA = sbase + stage * STAGE_BYTES;
        unsigned sB = sA + A_STAGE_BYTES;
#pragma unroll
        for (int ks = 0; ks < 4; ks++) {
            unsigned a[2][4];
#pragma unroll
            for (int mf = 0; mf < 2; mf++) {
                unsigned addr = sA + abase[mf] + (((unsigned)(ks * 32) + aK) ^ amask[mf]);
                ldsm4(addr, a[mf][0], a[mf][1], a[mf][2], a[mf][3]);
            }
            unsigned b[8][2];
#pragma unroll
            for (int fp = 0; fp < 4; fp++) {
                unsigned addr = sB + bbase[fp] + (((unsigned)(ks * 32) + bK) ^ bmask[fp]);
                ldsm4(addr, b[2*fp][0], b[2*fp][1], b[2*fp+1][0], b[2*fp+1][1]);
            }
#pragma unroll
            for (int nf = 0; nf < 8; nf++)
#pragma unroll
                for (int mf = 0; mf < 2; mf++)
                    mma16816(c[nf][mf], a[mf], b[nf]);
        }
    };

    load_chunk(0, 0);
#pragma unroll 1
    for (int ck = 0; ck < NCH; ck++) {
        if (ck + 1 < NCH) { load_chunk(ck + 1, (ck + 1) & 1); cp_wait<1>(); }
        else              { cp_wait<0>(); }
        __syncthreads();
        compute_chunk(ck & 1);
        __syncthreads();
    }

    // ---- write accumulators to smem P tile (aliases stage buffers) ----
    float* P = (float*)smem;
    {
        int rbase = wm * 32 + (lane >> 2);
        int cbase = wn * 64 + (lane & 3) * 2;
#pragma unroll
        for (int nf = 0; nf < 8; nf++) {
#pragma unroll
            for (int mf = 0; mf < 2; mf++) {
                int col = cbase + nf * 8;
                int rr = rbase + mf * 16;
                *(float2*)&P[rr * PSTRIDE + col]       = make_float2(c[nf][mf][0], c[nf][mf][1]);
                *(float2*)&P[(rr + 8) * PSTRIDE + col] = make_float2(c[nf][mf][2], c[nf][mf][3]);
            }
        }
    }
    __syncthreads();

    if (mode == 0) {
        for (int idx = tid; idx < MV * BN; idx += 256) {
            int r = (idx >> 7) + 1;
            int chl = idx & 127;
            int node = row0 + r - 1;
            if (node >= NN) continue;
            int ch = tn * BN + chl;
            float h = P[r * PSTRIDE + chl] + bias1[ch];
            size_t o = (size_t)t * RPAD * HD + (size_t)(node + 1) * HD + ch;
            Oh[o] = __float2half(h);
        }
    } else {
        const float w0 = g_tw[layer*5+0], w1 = g_tw[layer*5+1], w2 = g_tw[layer*5+2],
                    w3 = g_tw[layer*5+3], w4 = g_tw[layer*5+4];
        const float* bc = g_bcat + (layer*4 + t) * 2048 + tn * BN;
        for (int idx = tid; idx < MV * 16; idx += 256) {
            int r = (idx >> 4) + 1;
            int jc = idx & 15;
            int node = row0 + r - 1;
            if (node >= NN) continue;
            int col = jc * 8;
            const float* Pr = P + r * PSTRIDE;
            float plin = Pr[col + 0];
            float prl  = Pr[col + 1];
            float pc   = Pr[col + 2 - PSTRIDE] + Pr[col + 3] + Pr[col + 4 + PSTRIDE];
            float prc  = Pr[col + 5 - PSTRIDE] + Pr[col + 6] + Pr[col + 7 + PSTRIDE];
            int jg = tn * 16 + jc;
            size_t ia = (size_t)(row0 + r) * HD + jg;  // plane-relative
            float hold = __half2float(Ah[ia]);
            float h = w0 * fmaxf(plin + bc[col + 0], 0.f)
                    + w1 * fmaxf(prl  + bc[col + 1], 0.f)
                    + w2 * fmaxf(pc   + bc[col + 3], 0.f)
                    + w3 * fmaxf(prc  + bc[col + 6], 0.f)
                    + w4 * hold;
            size_t o = (size_t)t * RPAD * HD + (size_t)(node + 1) * HD + jg;
            Oh[o] = __float2half(h);
        }
    }
}

// ------------------- aggregation -------------------------------------------
__global__ void k_agg1() {
    int t = blockIdx.x >> 4;
    int chunk = blockIdx.x & 15;
    int ch = threadIdx.x;
    const h16* Hh = g_A + (size_t)t * RPAD * HD;
    float s = 0.f, mx = -3.4e38f;
    int n0 = chunk * 512;
    for (int n = n0; n < n0 + 512; n++) {
        float v = __half2float(Hh[(size_t)(n + 1) * HD + ch]);
        s += v;
        mx = fmaxf(mx, v);
    }
    g_psum[blockIdx.x * HD + ch] = s;
    g_pmax[blockIdx.x * HD + ch] = mx;
}

__global__ void k_agg2(const float* __restrict__ ow, const float* __restrict__ ob,
                       float* __restrict__ out) {
    __shared__ float agg[HD];
    int j = threadIdx.x;
    float s = 0.f, mx = -3.4e38f;
    for (int b = 0; b < 64; b++) {
        s += g_psum[b * HD + j];
        mx = fmaxf(mx, g_pmax[b * HD + j]);
    }
    agg[j] = g_aw[0] * s + g_aw[1] * (s / 32768.f) + g_aw[2] * mx;
    __syncthreads();
    if (j < 64) {
        float acc = ob[j];
        for (int k = 0; k < HD; k++) acc += agg[k] * ow[k * 64 + j];
        out[j] = acc;
    }
}

// ------------------- launcher ----------------------------------------------
extern "C" void kernel_launch(void* const* d_in, const int* in_sizes, int n_in,
                              void* d_out, int out_size) {
    (void)in_sizes; (void)n_in; (void)out_size;
    const float* x          = (const float*)d_in[0];
    const float* lin1_w     = (const float*)d_in[1];
    const float* lin1_b     = (const float*)d_in[2];
    const float* lin_w      = (const float*)d_in[3];
    const float* lin_b      = (const float*)d_in[4];
    const float* rel_lin_w  = (const float*)d_in[5];
    const float* rel_lin_b  = (const float*)d_in[6];
    const float* conv_w     = (const float*)d_in[7];
    const float* conv_b     = (const float*)d_in[8];
    const float* rel_conv_w = (const float*)d_in[9];
    const float* rel_conv_b = (const float*)d_in[10];
    const float* out_w      = (const float*)d_in[11];
    const float* out_b      = (const float*)d_in[12];
    const float* trans_arch = (const float*)d_in[13];
    const float* agg_arch   = (const float*)d_in[14];
    float* out = (float*)d_out;

    cudaFuncSetAttribute(k_gemm, cudaFuncAttributeMaxDynamicSharedMemorySize, SMEM_BYTES);

    k_prep<<<1, 32>>>(trans_arch, agg_arch);
    k_packx<<<4096, 256>>>(x);
    k_packw1<<<256, 256>>>(lin1_w);
    k_packwl<<<(8 * 2048 * 256 + 255) / 256, 256>>>(lin_w, lin_b, rel_lin_w, rel_lin_b,
                                                    conv_w, conv_b, rel_conv_w, rel_conv_b);

    dim3 g1(2, MT, TT), gl(16, MT, TT);
    // lin1: X -> A
    k_gemm<<<g1, 256, SMEM_BYTES>>>(0, 1, lin1_b, 0, 0);
    // layer 0: A -> B
    k_gemm<<<gl, 256, SMEM_BYTES>>>(1, 2, nullptr, 1, 0);
    // layer 1: B -> A
    k_gemm<<<gl, 256, SMEM_BYTES>>>(2, 1, nullptr, 1, 1);

    k_agg1<<<64, 256>>>();
    k_agg2<<<1, 256>>>(out_w, out_b, out);
}

// round 11
// speedup vs baseline: 2.7229x; 1.0545x over previous
#include <cuda_runtime.h>
#include <cuda_fp16.h>
#include <cstdint>

typedef __half h16;

#define TT 4
#define NN 8192
#define HD 256
#define RPAD 8320        // 1 zero halo row + 8192 data + tail pad (zero)
#define KT 256           // single fp16 term: K = 256
#define BM 128
#define BN 128
#define BK 64
#define NCH 4            // 256/64
#define MV 126           // valid output rows per M-tile
#define MT 66            // ceil(8192/126)
#define PSTRIDE 130
#define SMEM_BYTES (BM*PSTRIDE*4)            // 66560 (P tile; aliases stages)
#define STAGE_BYTES ((BM*BK + BN*BK)*2)      // 32768
#define A_STAGE_BYTES (BM*BK*2)              // 16384

// ------------------- device scratch (zero-initialized at load) -------------
__device__ __align__(256) h16 g_X[(size_t)TT*RPAD*HD];
__device__ __align__(256) h16 g_A[(size_t)TT*RPAD*HD];
__device__ __align__(256) h16 g_B[(size_t)TT*RPAD*HD];
__device__ __align__(256) h16 g_W1[HD*KT];
__device__ __align__(256) h16 g_WL[(size_t)8*2048*KT];
__device__ float g_bcat[8*2048];
__device__ float g_tw[10];
__device__ float g_aw[3];
__device__ float g_psum[HD];
__device__ float g_pmax[HD];

// ------------------- PTX helpers -------------------------------------------
__device__ __forceinline__ void cp_async16(unsigned dst, const void* src) {
    asm volatile("cp.async.cg.shared.global [%0], [%1], 16;\n" :: "r"(dst), "l"(src));
}
__device__ __forceinline__ void cp_commit() {
    asm volatile("cp.async.commit_group;\n" ::);
}
template <int N>
__device__ __forceinline__ void cp_wait() {
    asm volatile("cp.async.wait_group %0;\n" :: "n"(N));
}
__device__ __forceinline__ void ldsm4(unsigned addr, unsigned& r0, unsigned& r1,
                                      unsigned& r2, unsigned& r3) {
    asm volatile("ldmatrix.sync.aligned.m8n8.x4.shared.b16 {%0,%1,%2,%3}, [%4];\n"
                 : "=r"(r0), "=r"(r1), "=r"(r2), "=r"(r3) : "r"(addr));
}
__device__ __forceinline__ void mma16816(float c[4], const unsigned a[4], const unsigned b[2]) {
    asm volatile(
        "mma.sync.aligned.m16n8k16.row.col.f32.f16.f16.f32 "
        "{%0,%1,%2,%3}, {%4,%5,%6,%7}, {%8,%9}, {%0,%1,%2,%3};\n"
        : "+f"(c[0]), "+f"(c[1]), "+f"(c[2]), "+f"(c[3])
        : "r"(a[0]), "r"(a[1]), "r"(a[2]), "r"(a[3]), "r"(b[0]), "r"(b[1]));
}
__device__ __forceinline__ unsigned swz(unsigned b) { return b ^ ((b >> 3) & 0x70); }

__device__ __forceinline__ void atomicMaxFloat(float* addr, float val) {
    if (val >= 0.f) atomicMax((int*)addr, __float_as_int(val));
    else            atomicMin((unsigned int*)addr, (unsigned int)__float_as_int(val));
}

__device__ __forceinline__ h16* sel_buf(int s) { return s==0 ? g_X : (s==1 ? g_A : g_B); }

// ------------------- prep kernels ------------------------------------------
// k_packx: converts x -> fp16 padded layout; also packs lin1_w and resets
// the aggregation accumulators (needed each graph replay).
__global__ void k_packx(const float* __restrict__ x, const float* __restrict__ w1) {
    size_t gid = (size_t)blockIdx.x * blockDim.x + threadIdx.x;
    if (gid < 65536) {
        int n = (int)(gid >> 8), k = (int)(gid & 255);
        g_W1[n*KT + k] = __float2half(w1[k * HD + n]);  // lin1_w[k][n]
    }
    if (gid < 256) {
        g_psum[gid] = 0.f;
        g_pmax[gid] = -3.4e38f;
    }
    size_t total = (size_t)TT * RPAD * HD;
    for (size_t i = gid; i < total; i += (size_t)gridDim.x * blockDim.x) {
        int ch = (int)(i & 255);
        size_t row = i >> 8;                 // t*RPAD + p
        int p = (int)(row % RPAD);
        float v = 0.f;
        int n = p - 1;
        if (n >= 0 && n < NN) {
            int t = (int)(row / RPAD);
            v = x[((size_t)t * NN + n) * HD + ch];
        }
        g_X[i] = __float2half(v);
    }
}

// k_packwl: packs all layer weights; block 0 thread 0 also computes the
// softmax arch weights (tiny).
__global__ void k_packwl(const float* __restrict__ lw,  const float* __restrict__ lb,
                         const float* __restrict__ rlw, const float* __restrict__ rlb,
                         const float* __restrict__ cw,  const float* __restrict__ cb,
                         const float* __restrict__ rcw, const float* __restrict__ rcb,
                         const float* __restrict__ ta,  const float* __restrict__ aa) {
    if (blockIdx.x == 0 && threadIdx.x == 0) {
        for (int l = 0; l < 2; l++) {
            float m = -1e30f;
            for (int i = 0; i < 5; i++) m = fmaxf(m, ta[l*5+i]);
            float e[5], s = 0.f;
            for (int i = 0; i < 5; i++) { e[i] = expf(ta[l*5+i] - m); s += e[i]; }
            for (int i = 0; i < 5; i++) g_tw[l*5+i] = e[i] / s;
        }
        float m = -1e30f;
        for (int i = 0; i < 3; i++) m = fmaxf(m, aa[i]);
        float e[3], s = 0.f;
        for (int i = 0; i < 3; i++) { e[i] = expf(aa[i] - m); s += e[i]; }
        for (int i = 0; i < 3; i++) g_aw[i] = e[i] / s;
    }
    size_t i = (size_t)blockIdx.x * blockDim.x + threadIdx.x;  // over 8*2048*256
    if (i >= (size_t)8 * 2048 * 256) return;
    int k  = (int)(i & 255);
    int n  = (int)((i >> 8) & 2047);
    int lt = (int)(i >> 19);         // 0..7
    int l = lt >> 2, t = lt & 3;
    int j = n >> 3, op = n & 7;
    float v;
    if (op == 0)      v = lw[(l*256 + k)*256 + j];
    else if (op == 1) v = rlw[((l*4 + t)*256 + k)*256 + j];
    else if (op < 5)  { int kk = op - 2; v = cw[((l*256 + j)*256 + k)*3 + kk]; }
    else              { int kk = op - 5; v = rcw[(((l*4 + t)*256 + j)*256 + k)*3 + kk]; }
    g_WL[((size_t)lt * 2048 + n) * KT + k] = __float2half(v);
    if (k == 0) {
        float b = 0.f;
        if (op == 0)      b = lb[l*256 + j];
        else if (op == 1) b = rlb[(l*4 + t)*256 + j];
        else if (op == 3) b = cb[l*256 + j];
        else if (op == 6) b = rcb[(l*4 + t)*256 + j];
        g_bcat[lt*2048 + n] = b;
    }
}

// ------------------- fused GEMM + epilogue ---------------------------------
// P[128 x 128] = A[128 x 256] * B[128 x 256]^T, fp16 operands, fp32 accumulate
// mode 0: lin1 (tn tile covers 128 of 256 channels, bias only)
// mode 1: layer (tn tile covers 16 channels x 8 op taps; relu/conv/identity mix)
//         layer==1 additionally accumulates the global sum/max aggregation.
// 256 threads, 2 CTAs/SM: second CTA's mainloop hides this CTA's bubbles.
__global__ void __launch_bounds__(256, 2)
k_gemm(int abuf, int obuf, const float* __restrict__ bias1, int mode, int layer) {
    extern __shared__ char smem[];
    const int tid = threadIdx.x;
    const int wid = tid >> 5, lane = tid & 31;
    const int tn = blockIdx.x, tm = blockIdx.y, t = blockIdx.z;

    const h16* Ah = sel_buf(abuf) + (size_t)t * RPAD * HD;
    const h16* Bp = mode ? (g_WL + ((size_t)(layer*4 + t) * 2048 + (size_t)tn * BN) * KT)
                         : (g_W1 + (size_t)tn * BN * KT);
    h16* Oh = sel_buf(obuf);

    const int row0 = tm * MV;   // global padded row of A-tile row 0
    unsigned sbase = (unsigned)__cvta_generic_to_shared(smem);

    float c[8][2][4];
#pragma unroll
    for (int a = 0; a < 8; a++)
#pragma unroll
        for (int b = 0; b < 2; b++)
#pragma unroll
            for (int i = 0; i < 4; i++) c[a][b][i] = 0.f;

    auto load_chunk = [&](int ck, int stage) {
        unsigned sA = sbase + stage * STAGE_BYTES;
        unsigned sB = sA + A_STAGE_BYTES;
        int kofs = ck * 64;
#pragma unroll
        for (int i = 0; i < 4; i++) {
            int idx = tid + i * 256;          // 0..1023 (128 rows x 8 cols)
            int r = idx >> 3, cc = idx & 7;
            const h16* src = Ah + (size_t)(row0 + r) * HD + kofs + cc * 8;
            cp_async16(sA + swz((unsigned)(r * 128 + cc * 16)), src);
        }
#pragma unroll
        for (int i = 0; i < 4; i++) {
            int idx = tid + i * 256;          // 0..1023
            int r = idx >> 3, cc = idx & 7;
            const h16* src = Bp + (size_t)r * KT + kofs + cc * 8;
            cp_async16(sB + swz((unsigned)(r * 128 + cc * 16)), src);
        }
        cp_commit();
    };

    // ldmatrix address bases (k-offset XOR mask depends only on row)
    const int wm = wid & 3, wn = wid >> 2;   // wm: 4 x 32 rows, wn: 2 x 64 cols
    unsigned abase[2], amask[2], bbase[4], bmask[4];
    const unsigned aK = (unsigned)((lane >> 4) * 16);        // bytes
    const unsigned bK = (unsigned)(((lane >> 3) & 1) * 16);  // bytes
    {
        int r = wm * 32 + ((lane >> 3) & 1) * 8 + (lane & 7);
#pragma unroll
        for (int mf = 0; mf < 2; mf++) {
            unsigned rb = (unsigned)((r + mf * 16) * 128);
            abase[mf] = rb;
            amask[mf] = (rb >> 3) & 0x70;
        }
        int nr = wn * 64 + (lane >> 4) * 8 + (lane & 7);
#pragma unroll
        for (int fp = 0; fp < 4; fp++) {
            unsigned rb = (unsigned)((nr + fp * 16) * 128);
            bbase[fp] = rb;
            bmask[fp] = (rb >> 3) & 0x70;
        }
    }

    auto compute_chunk = [&](int stage) {
        unsigned sA = sbase + stage * STAGE_BYTES;
        unsigned sB = sA + A_STAGE_BYTES;
#pragma unroll
        for (int ks = 0; ks < 4; ks++) {
            unsigned a[2][4];
#pragma unroll
            for (int mf = 0; mf < 2; mf++) {
                unsigned addr = sA + abase[mf] + (((unsigned)(ks * 32) + aK) ^ amask[mf]);
                ldsm4(addr, a[mf][0], a[mf][1], a[mf][2], a[mf][3]);
            }
            unsigned b[8][2];
#pragma unroll
            for (int fp = 0; fp < 4; fp++) {
                unsigned addr = sB + bbase[fp] + (((unsigned)(ks * 32) + bK) ^ bmask[fp]);
                ldsm4(addr, b[2*fp][0], b[2*fp][1], b[2*fp+1][0], b[2*fp+1][1]);
            }
#pragma unroll
            for (int nf = 0; nf < 8; nf++)
#pragma unroll
                for (int mf = 0; mf < 2; mf++)
                    mma16816(c[nf][mf], a[mf], b[nf]);
        }
    };

    load_chunk(0, 0);
#pragma unroll 1
    for (int ck = 0; ck < NCH; ck++) {
        if (ck + 1 < NCH) { load_chunk(ck + 1, (ck + 1) & 1); cp_wait<1>(); }
        else              { cp_wait<0>(); }
        __syncthreads();
        compute_chunk(ck & 1);
        __syncthreads();
    }

    // ---- prefetch identity term (independent of P) before the smem turnover
    float hold[8];
    if (mode == 1) {
#pragma unroll
        for (int i = 0; i < 8; i++) {
            int idx = tid + i * 256;
            if (idx < MV * 16) {
                int r = (idx >> 4) + 1;
                int jg = tn * 16 + (idx & 15);
                hold[i] = __half2float(Ah[(size_t)(row0 + r) * HD + jg]);
            }
        }
    }

    // ---- write accumulators to smem P tile (aliases stage buffers) ----
    float* P = (float*)smem;
    {
        int rbase = wm * 32 + (lane >> 2);
        int cbase = wn * 64 + (lane & 3) * 2;
#pragma unroll
        for (int nf = 0; nf < 8; nf++) {
#pragma unroll
            for (int mf = 0; mf < 2; mf++) {
                int col = cbase + nf * 8;
                int rr = rbase + mf * 16;
                *(float2*)&P[rr * PSTRIDE + col]       = make_float2(c[nf][mf][0], c[nf][mf][1]);
                *(float2*)&P[(rr + 8) * PSTRIDE + col] = make_float2(c[nf][mf][2], c[nf][mf][3]);
            }
        }
    }
    __syncthreads();

    if (mode == 0) {
        for (int idx = tid; idx < MV * BN; idx += 256) {
            int r = (idx >> 7) + 1;
            int chl = idx & 127;
            int node = row0 + r - 1;
            if (node >= NN) continue;
            int ch = tn * BN + chl;
            float h = P[r * PSTRIDE + chl] + bias1[ch];
            size_t o = (size_t)t * RPAD * HD + (size_t)(node + 1) * HD + ch;
            Oh[o] = __float2half(h);
        }
    } else {
        const float w0 = g_tw[layer*5+0], w1 = g_tw[layer*5+1], w2 = g_tw[layer*5+2],
                    w3 = g_tw[layer*5+3], w4 = g_tw[layer*5+4];
        const float* bc = g_bcat + (layer*4 + t) * 2048 + tn * BN;
        float accS = 0.f, accM = -3.4e38f;
#pragma unroll
        for (int i = 0; i < 8; i++) {
            int idx = tid + i * 256;
            if (idx >= MV * 16) break;
            int r = (idx >> 4) + 1;
            int jc = idx & 15;
            int node = row0 + r - 1;
            if (node >= NN) continue;
            int col = jc * 8;
            const float* Pr = P + r * PSTRIDE;
            float plin = Pr[col + 0];
            float prl  = Pr[col + 1];
            float pc   = Pr[col + 2 - PSTRIDE] + Pr[col + 3] + Pr[col + 4 + PSTRIDE];
            float prc  = Pr[col + 5 - PSTRIDE] + Pr[col + 6] + Pr[col + 7 + PSTRIDE];
            int jg = tn * 16 + jc;
            float h = w0 * fmaxf(plin + bc[col + 0], 0.f)
                    + w1 * fmaxf(prl  + bc[col + 1], 0.f)
                    + w2 * fmaxf(pc   + bc[col + 3], 0.f)
                    + w3 * fmaxf(prc  + bc[col + 6], 0.f)
                    + w4 * hold[i];
            size_t o = (size_t)t * RPAD * HD + (size_t)(node + 1) * HD + jg;
            Oh[o] = __float2half(h);
            if (layer == 1) { accS += h; accM = fmaxf(accM, h); }
        }
        if (layer == 1) {
            __syncthreads();                 // everyone done reading P
            float* R = (float*)smem;         // reuse smem for reduction
            R[tid]       = accS;
            R[256 + tid] = accM;
            __syncthreads();
            if (tid < 16) {                  // tid == jc
                float s = 0.f, m = -3.4e38f;
#pragma unroll
                for (int g = 0; g < 16; g++) {
                    s += R[g * 16 + tid];
                    m = fmaxf(m, R[256 + g * 16 + tid]);
                }
                int ch = tn * 16 + tid;
                atomicAdd(&g_psum[ch], s);
                atomicMaxFloat(&g_pmax[ch], m);
            }
        }
    }
}

// ------------------- final head --------------------------------------------
__global__ void k_agg2(const float* __restrict__ ow, const float* __restrict__ ob,
                       float* __restrict__ out) {
    __shared__ float agg[HD];
    int j = threadIdx.x;
    float s  = g_psum[j];
    float mx = g_pmax[j];
    agg[j] = g_aw[0] * s + g_aw[1] * (s / 32768.f) + g_aw[2] * mx;
    __syncthreads();
    if (j < 64) {
        float acc = ob[j];
        for (int k = 0; k < HD; k++) acc += agg[k] * ow[k * 64 + j];
        out[j] = acc;
    }
}

// ------------------- launcher ----------------------------------------------
extern "C" void kernel_launch(void* const* d_in, const int* in_sizes, int n_in,
                              void* d_out, int out_size) {
    (void)in_sizes; (void)n_in; (void)out_size;
    const float* x          = (const float*)d_in[0];
    const float* lin1_w     = (const float*)d_in[1];
    const float* lin1_b     = (const float*)d_in[2];
    const float* lin_w      = (const float*)d_in[3];
    const float* lin_b      = (const float*)d_in[4];
    const float* rel_lin_w  = (const float*)d_in[5];
    const float* rel_lin_b  = (const float*)d_in[6];
    const float* conv_w     = (const float*)d_in[7];
    const float* conv_b     = (const float*)d_in[8];
    const float* rel_conv_w = (const float*)d_in[9];
    const float* rel_conv_b = (const float*)d_in[10];
    const float* out_w      = (const float*)d_in[11];
    const float* out_b      = (const float*)d_in[12];
    const float* trans_arch = (const float*)d_in[13];
    const float* agg_arch   = (const float*)d_in[14];
    float* out = (float*)d_out;

    cudaFuncSetAttribute(k_gemm, cudaFuncAttributeMaxDynamicSharedMemorySize, SMEM_BYTES);

    k_packx<<<4096, 256>>>(x, lin1_w);
    k_packwl<<<(8 * 2048 * 256 + 255) / 256, 256>>>(lin_w, lin_b, rel_lin_w, rel_lin_b,
                                                    conv_w, conv_b, rel_conv_w, rel_conv_b,
                                                    trans_arch, agg_arch);

    dim3 g1(2, MT, TT), gl(16, MT, TT);
    // lin1: X -> A
    k_gemm<<<g1, 256, SMEM_BYTES>>>(0, 1, lin1_b, 0, 0);
    // layer 0: A -> B
    k_gemm<<<gl, 256, SMEM_BYTES>>>(1, 2, nullptr, 1, 0);
    // layer 1: B -> A (fused global aggregation)
    k_gemm<<<gl, 256, SMEM_BYTES>>>(2, 1, nullptr, 1, 1);

    k_agg2<<<1, 256>>>(out_w, out_b, out);
}

// round 12
// speedup vs baseline: 2.9110x; 1.0691x over previous
#include <cuda_runtime.h>
#include <cuda_fp16.h>
#include <cstdint>

typedef __half h16;

#define TT 4
#define NN 8192
#define HD 256
#define RPAD 8320        // 1 zero halo row + 8192 data + tail pad (zero)
#define KT 256           // single fp16 term: K = 256
#define BM 128
#define BN 128
#define BK 64
#define NCH 4            // 256/64
#define MV 126           // valid output rows per M-tile
#define MT 66            // ceil(8192/126)
#define PSTRIDE 130
#define NTHR 128
#define SMEM_BYTES (BM*PSTRIDE*4)            // 66560 (P tile; aliases stages)
#define STAGE_BYTES ((BM*BK + BN*BK)*2)      // 32768
#define A_STAGE_BYTES (BM*BK*2)              // 16384

// ------------------- device scratch (zero-initialized at load) -------------
__device__ __align__(256) h16 g_X[(size_t)TT*RPAD*HD];
__device__ __align__(256) h16 g_A[(size_t)TT*RPAD*HD];
__device__ __align__(256) h16 g_B[(size_t)TT*RPAD*HD];
__device__ __align__(256) h16 g_W1[HD*KT];
__device__ __align__(256) h16 g_WL[(size_t)8*2048*KT];
__device__ float g_bcat[8*2048];
__device__ float g_tw[10];
__device__ float g_aw[3];
__device__ float g_psum[HD];
__device__ float g_pmax[HD];

// ------------------- PTX helpers -------------------------------------------
__device__ __forceinline__ void cp_async16(unsigned dst, const void* src) {
    asm volatile("cp.async.cg.shared.global [%0], [%1], 16;\n" :: "r"(dst), "l"(src));
}
__device__ __forceinline__ void cp_commit() {
    asm volatile("cp.async.commit_group;\n" ::);
}
template <int N>
__device__ __forceinline__ void cp_wait() {
    asm volatile("cp.async.wait_group %0;\n" :: "n"(N));
}
__device__ __forceinline__ void ldsm4(unsigned addr, unsigned& r0, unsigned& r1,
                                      unsigned& r2, unsigned& r3) {
    asm volatile("ldmatrix.sync.aligned.m8n8.x4.shared.b16 {%0,%1,%2,%3}, [%4];\n"
                 : "=r"(r0), "=r"(r1), "=r"(r2), "=r"(r3) : "r"(addr));
}
__device__ __forceinline__ void mma16816(float c[4], const unsigned a[4], const unsigned b[2]) {
    asm volatile(
        "mma.sync.aligned.m16n8k16.row.col.f32.f16.f16.f32 "
        "{%0,%1,%2,%3}, {%4,%5,%6,%7}, {%8,%9}, {%0,%1,%2,%3};\n"
        : "+f"(c[0]), "+f"(c[1]), "+f"(c[2]), "+f"(c[3])
        : "r"(a[0]), "r"(a[1]), "r"(a[2]), "r"(a[3]), "r"(b[0]), "r"(b[1]));
}
__device__ __forceinline__ unsigned swz(unsigned b) { return b ^ ((b >> 3) & 0x70); }

__device__ __forceinline__ void atomicMaxFloat(float* addr, float val) {
    if (val >= 0.f) atomicMax((int*)addr, __float_as_int(val));
    else            atomicMin((unsigned int*)addr, (unsigned int)__float_as_int(val));
}

__device__ __forceinline__ h16* sel_buf(int s) { return s==0 ? g_X : (s==1 ? g_A : g_B); }

// ------------------- prep kernels ------------------------------------------
// k_packx: converts x -> fp16 padded layout; also packs lin1_w and resets
// the aggregation accumulators (needed each graph replay).
__global__ void k_packx(const float* __restrict__ x, const float* __restrict__ w1) {
    size_t gid = (size_t)blockIdx.x * blockDim.x + threadIdx.x;
    if (gid < 65536) {
        int n = (int)(gid >> 8), k = (int)(gid & 255);
        g_W1[n*KT + k] = __float2half(w1[k * HD + n]);  // lin1_w[k][n]
    }
    if (gid < 256) {
        g_psum[gid] = 0.f;
        g_pmax[gid] = -3.4e38f;
    }
    size_t total = (size_t)TT * RPAD * HD;
    for (size_t i = gid; i < total; i += (size_t)gridDim.x * blockDim.x) {
        int ch = (int)(i & 255);
        size_t row = i >> 8;                 // t*RPAD + p
        int p = (int)(row % RPAD);
        float v = 0.f;
        int n = p - 1;
        if (n >= 0 && n < NN) {
            int t = (int)(row / RPAD);
            v = x[((size_t)t * NN + n) * HD + ch];
        }
        g_X[i] = __float2half(v);
    }
}

// k_packwl: packs all layer weights; block 0 thread 0 also computes the
// softmax arch weights (tiny).
__global__ void k_packwl(const float* __restrict__ lw,  const float* __restrict__ lb,
                         const float* __restrict__ rlw, const float* __restrict__ rlb,
                         const float* __restrict__ cw,  const float* __restrict__ cb,
                         const float* __restrict__ rcw, const float* __restrict__ rcb,
                         const float* __restrict__ ta,  const float* __restrict__ aa) {
    if (blockIdx.x == 0 && threadIdx.x == 0) {
        for (int l = 0; l < 2; l++) {
            float m = -1e30f;
            for (int i = 0; i < 5; i++) m = fmaxf(m, ta[l*5+i]);
            float e[5], s = 0.f;
            for (int i = 0; i < 5; i++) { e[i] = expf(ta[l*5+i] - m); s += e[i]; }
            for (int i = 0; i < 5; i++) g_tw[l*5+i] = e[i] / s;
        }
        float m = -1e30f;
        for (int i = 0; i < 3; i++) m = fmaxf(m, aa[i]);
        float e[3], s = 0.f;
        for (int i = 0; i < 3; i++) { e[i] = expf(aa[i] - m); s += e[i]; }
        for (int i = 0; i < 3; i++) g_aw[i] = e[i] / s;
    }
    size_t i = (size_t)blockIdx.x * blockDim.x + threadIdx.x;  // over 8*2048*256
    if (i >= (size_t)8 * 2048 * 256) return;
    int k  = (int)(i & 255);
    int n  = (int)((i >> 8) & 2047);
    int lt = (int)(i >> 19);         // 0..7
    int l = lt >> 2, t = lt & 3;
    int j = n >> 3, op = n & 7;
    float v;
    if (op == 0)      v = lw[(l*256 + k)*256 + j];
    else if (op == 1) v = rlw[((l*4 + t)*256 + k)*256 + j];
    else if (op < 5)  { int kk = op - 2; v = cw[((l*256 + j)*256 + k)*3 + kk]; }
    else              { int kk = op - 5; v = rcw[(((l*4 + t)*256 + j)*256 + k)*3 + kk]; }
    g_WL[((size_t)lt * 2048 + n) * KT + k] = __float2half(v);
    if (k == 0) {
        float b = 0.f;
        if (op == 0)      b = lb[l*256 + j];
        else if (op == 1) b = rlb[(l*4 + t)*256 + j];
        else if (op == 3) b = cb[l*256 + j];
        else if (op == 6) b = rcb[(l*4 + t)*256 + j];
        g_bcat[lt*2048 + n] = b;
    }
}

// ------------------- fused GEMM + epilogue ---------------------------------
// P[128 x 128] = A[128 x 256] * B[128 x 256]^T, fp16 operands, fp32 accumulate
// 128 threads, 4 warps, 64x64 warp tiles (128 B of smem per MMA vs 192 before),
// 2 CTAs/SM.  mode 0: lin1; mode 1: layer epilogue (+ aggregation on layer 1).
__global__ void __launch_bounds__(NTHR, 2)
k_gemm(int abuf, int obuf, const float* __restrict__ bias1, int mode, int layer) {
    extern __shared__ char smem[];
    const int tid = threadIdx.x;
    const int wid = tid >> 5, lane = tid & 31;
    const int tn = blockIdx.x, tm = blockIdx.y, t = blockIdx.z;

    const h16* Ah = sel_buf(abuf) + (size_t)t * RPAD * HD;
    const h16* Bp = mode ? (g_WL + ((size_t)(layer*4 + t) * 2048 + (size_t)tn * BN) * KT)
                         : (g_W1 + (size_t)tn * BN * KT);
    h16* Oh = sel_buf(obuf);

    const int row0 = tm * MV;   // global padded row of A-tile row 0
    unsigned sbase = (unsigned)__cvta_generic_to_shared(smem);

    float c[8][4][4];
#pragma unroll
    for (int a = 0; a < 8; a++)
#pragma unroll
        for (int b = 0; b < 4; b++)
#pragma unroll
            for (int i = 0; i < 4; i++) c[a][b][i] = 0.f;

    auto load_chunk = [&](int ck, int stage) {
        unsigned sA = sbase + stage * STAGE_BYTES;
        unsigned sB = sA + A_STAGE_BYTES;
        int kofs = ck * 64;
#pragma unroll
        for (int i = 0; i < 8; i++) {
            int idx = tid + i * NTHR;         // 0..1023 (128 rows x 8 col-groups)
            int r = idx >> 3, cc = idx & 7;
            const h16* src = Ah + (size_t)(row0 + r) * HD + kofs + cc * 8;
            cp_async16(sA + swz((unsigned)(r * 128 + cc * 16)), src);
        }
#pragma unroll
        for (int i = 0; i < 8; i++) {
            int idx = tid + i * NTHR;         // 0..1023
            int r = idx >> 3, cc = idx & 7;
            const h16* src = Bp + (size_t)r * KT + kofs + cc * 8;
            cp_async16(sB + swz((unsigned)(r * 128 + cc * 16)), src);
        }
        cp_commit();
    };

    // warp tiling: wm in {0,1} -> 64 rows; wn in {0,1} -> 64 cols
    const int wm = wid & 1, wn = (wid >> 1) & 1;
    unsigned abase[4], amask[4], bbase[4], bmask[4];
    const unsigned aK = (unsigned)((lane >> 4) * 16);        // bytes
    const unsigned bK = (unsigned)(((lane >> 3) & 1) * 16);  // bytes
    {
        int r = wm * 64 + ((lane >> 3) & 1) * 8 + (lane & 7);
#pragma unroll
        for (int mf = 0; mf < 4; mf++) {
            unsigned rb = (unsigned)((r + mf * 16) * 128);
            abase[mf] = rb;
            amask[mf] = (rb >> 3) & 0x70;
        }
        int nr = wn * 64 + (lane >> 4) * 8 + (lane & 7);
#pragma unroll
        for (int fp = 0; fp < 4; fp++) {
            unsigned rb = (unsigned)((nr + fp * 16) * 128);
            bbase[fp] = rb;
            bmask[fp] = (rb >> 3) & 0x70;
        }
    }

    auto compute_chunk = [&](int stage) {
        unsigned sA = sbase + stage * STAGE_BYTES;
        unsigned sB = sA + A_STAGE_BYTES;
#pragma unroll
        for (int ks = 0; ks < 4; ks++) {
            unsigned a[4][4];
#pragma unroll
            for (int mf = 0; mf < 4; mf++) {
                unsigned addr = sA + abase[mf] + (((unsigned)(ks * 32) + aK) ^ amask[mf]);
                ldsm4(addr, a[mf][0], a[mf][1], a[mf][2], a[mf][3]);
            }
            unsigned b[8][2];
#pragma unroll
            for (int fp = 0; fp < 4; fp++) {
                unsigned addr = sB + bbase[fp] + (((unsigned)(ks * 32) + bK) ^ bmask[fp]);
                ldsm4(addr, b[2*fp][0], b[2*fp][1], b[2*fp+1][0], b[2*fp+1][1]);
            }
#pragma unroll
            for (int nf = 0; nf < 8; nf++)
#pragma unroll
                for (int mf = 0; mf < 4; mf++)
                    mma16816(c[nf][mf], a[mf], b[nf]);
        }
    };

    load_chunk(0, 0);
#pragma unroll 1
    for (int ck = 0; ck < NCH; ck++) {
        if (ck + 1 < NCH) { load_chunk(ck + 1, (ck + 1) & 1); cp_wait<1>(); }
        else              { cp_wait<0>(); }
        __syncthreads();
        compute_chunk(ck & 1);
        __syncthreads();
    }

    // ---- prefetch identity term (independent of P) before the smem turnover
    float hold[16];
    if (mode == 1) {
#pragma unroll
        for (int i = 0; i < 16; i++) {
            int idx = tid + i * NTHR;
            if (idx < MV * 16) {
                int r = (idx >> 4) + 1;
                int jg = tn * 16 + (idx & 15);
                hold[i] = __half2float(Ah[(size_t)(row0 + r) * HD + jg]);
            }
        }
    }

    // ---- write accumulators to smem P tile (aliases stage buffers) ----
    float* P = (float*)smem;
    {
        int rbase = wm * 64 + (lane >> 2);
        int cbase = wn * 64 + (lane & 3) * 2;
#pragma unroll
        for (int nf = 0; nf < 8; nf++) {
#pragma unroll
            for (int mf = 0; mf < 4; mf++) {
                int col = cbase + nf * 8;
                int rr = rbase + mf * 16;
                *(float2*)&P[rr * PSTRIDE + col]       = make_float2(c[nf][mf][0], c[nf][mf][1]);
                *(float2*)&P[(rr + 8) * PSTRIDE + col] = make_float2(c[nf][mf][2], c[nf][mf][3]);
            }
        }
    }
    __syncthreads();

    if (mode == 0) {
        for (int idx = tid; idx < MV * BN; idx += NTHR) {
            int r = (idx >> 7) + 1;
            int chl = idx & 127;
            int node = row0 + r - 1;
            if (node >= NN) continue;
            int ch = tn * BN + chl;
            float h = P[r * PSTRIDE + chl] + bias1[ch];
            size_t o = (size_t)t * RPAD * HD + (size_t)(node + 1) * HD + ch;
            Oh[o] = __float2half(h);
        }
    } else {
        const float w0 = g_tw[layer*5+0], w1 = g_tw[layer*5+1], w2 = g_tw[layer*5+2],
                    w3 = g_tw[layer*5+3], w4 = g_tw[layer*5+4];
        const float* bc = g_bcat + (layer*4 + t) * 2048 + tn * BN;
        float accS = 0.f, accM = -3.4e38f;
#pragma unroll
        for (int i = 0; i < 16; i++) {
            int idx = tid + i * NTHR;
            if (idx >= MV * 16) break;
            int r = (idx >> 4) + 1;
            int jc = idx & 15;
            int node = row0 + r - 1;
            if (node >= NN) continue;
            int col = jc * 8;
            const float* Pr = P + r * PSTRIDE;
            float plin = Pr[col + 0];
            float prl  = Pr[col + 1];
            float pc   = Pr[col + 2 - PSTRIDE] + Pr[col + 3] + Pr[col + 4 + PSTRIDE];
            float prc  = Pr[col + 5 - PSTRIDE] + Pr[col + 6] + Pr[col + 7 + PSTRIDE];
            int jg = tn * 16 + jc;
            float h = w0 * fmaxf(plin + bc[col + 0], 0.f)
                    + w1 * fmaxf(prl  + bc[col + 1], 0.f)
                    + w2 * fmaxf(pc   + bc[col + 3], 0.f)
                    + w3 * fmaxf(prc  + bc[col + 6], 0.f)
                    + w4 * hold[i];
            size_t o = (size_t)t * RPAD * HD + (size_t)(node + 1) * HD + jg;
            Oh[o] = __float2half(h);
            if (layer == 1) { accS += h; accM = fmaxf(accM, h); }
        }
        if (layer == 1) {
            __syncthreads();                 // everyone done reading P
            float* R = (float*)smem;         // reuse smem for reduction
            R[tid]        = accS;
            R[NTHR + tid] = accM;
            __syncthreads();
            if (tid < 16) {                  // tid == jc
                float s = 0.f, m = -3.4e38f;
#pragma unroll
                for (int g = 0; g < NTHR / 16; g++) {
                    s += R[g * 16 + tid];
                    m = fmaxf(m, R[NTHR + g * 16 + tid]);
                }
                int ch = tn * 16 + tid;
                atomicAdd(&g_psum[ch], s);
                atomicMaxFloat(&g_pmax[ch], m);
            }
        }
    }
}

// ------------------- final head --------------------------------------------
__global__ void k_agg2(const float* __restrict__ ow, const float* __restrict__ ob,
                       float* __restrict__ out) {
    __shared__ float agg[HD];
    int j = threadIdx.x;
    float s  = g_psum[j];
    float mx = g_pmax[j];
    agg[j] = g_aw[0] * s + g_aw[1] * (s / 32768.f) + g_aw[2] * mx;
    __syncthreads();
    if (j < 64) {
        float acc = ob[j];
        for (int k = 0; k < HD; k++) acc += agg[k] * ow[k * 64 + j];
        out[j] = acc;
    }
}

// ------------------- launcher ----------------------------------------------
extern "C" void kernel_launch(void* const* d_in, const int* in_sizes, int n_in,
                              void* d_out, int out_size) {
    (void)in_sizes; (void)n_in; (void)out_size;
    const float* x          = (const float*)d_in[0];
    const float* lin1_w     = (const float*)d_in[1];
    const float* lin1_b     = (const float*)d_in[2];
    const float* lin_w      = (const float*)d_in[3];
    const float* lin_b      = (const float*)d_in[4];
    const float* rel_lin_w  = (const float*)d_in[5];
    const float* rel_lin_b  = (const float*)d_in[6];
    const float* conv_w     = (const float*)d_in[7];
    const float* conv_b     = (const float*)d_in[8];
    const float* rel_conv_w = (const float*)d_in[9];
    const float* rel_conv_b = (const float*)d_in[10];
    const float* out_w      = (const float*)d_in[11];
    const float* out_b      = (const float*)d_in[12];
    const float* trans_arch = (const float*)d_in[13];
    const float* agg_arch   = (const float*)d_in[14];
    float* out = (float*)d_out;

    cudaFuncSetAttribute(k_gemm, cudaFuncAttributeMaxDynamicSharedMemorySize, SMEM_BYTES);

    k_packx<<<4096, 256>>>(x, lin1_w);
    k_packwl<<<(8 * 2048 * 256 + 255) / 256, 256>>>(lin_w, lin_b, rel_lin_w, rel_lin_b,
                                                    conv_w, conv_b, rel_conv_w, rel_conv_b,
                                                    trans_arch, agg_arch);

    dim3 g1(2, MT, TT), gl(16, MT, TT);
    // lin1: X -> A
    k_gemm<<<g1, NTHR, SMEM_BYTES>>>(0, 1, lin1_b, 0, 0);
    // layer 0: A -> B
    k_gemm<<<gl, NTHR, SMEM_BYTES>>>(1, 2, nullptr, 1, 0);
    // layer 1: B -> A (fused global aggregation)
    k_gemm<<<gl, NTHR, SMEM_BYTES>>>(2, 1, nullptr, 1, 1);

    k_agg2<<<1, 256>>>(out_w, out_b, out);
}